// round 7
// baseline (speedup 1.0000x reference)
#include <cuda_runtime.h>
#include <cuda_fp16.h>
#include <cstdint>
#include <cstddef>

#define S_DIM 2048
#define DIN 4096
#define DOUT 11008
#define REMAINED 3852

// Eigen multithread-branch blocking: kc = min((l1-ksub)/kdiv, 320) & ~7 = 320
// Panels: 12 x 320 + tail 256. In BKC=16 units: join after c = 19,39,...,239.
#define KC_BLOCKS 20          // 320 / 16

// Output layout (float32 concat): tv | filtered_W | filtered_bias | indices
#define OFF_TV   ((size_t)0)
#define N_TV     ((size_t)S_DIM * DOUT)
#define OFF_W    (N_TV)
#define N_W      ((size_t)REMAINED * DIN)
#define OFF_BIAS (OFF_W + N_W)
#define OFF_IDX  (OFF_BIAS + REMAINED)

// Scratch (device globals — no allocation allowed)
__device__ int g_counts[DOUT];
__device__ int g_pos;
__device__ int g_limit;
__device__ int g_indices[REMAINED];

// ---------------------------------------------------------------------------
// init: zero counts + pos (required every call: graph replays)
// ---------------------------------------------------------------------------
__global__ void init_kernel() {
    int i = blockIdx.x * blockDim.x + threadIdx.x;
    if (i < DOUT) g_counts[i] = 0;
    if (i == 0) g_pos = 0;
}

// ---------------------------------------------------------------------------
// Eigen-order GEMM: per element,
//   accT = (((p0) + p1) + ... + p12)  where pt = ascending-k FMA chain over
//   panel t (kc=320, tail 256), all f32. Then tv = f16(f16(accT) + bias).
// Block: 512 threads, tile 128(M) x 128(N), k-chunk 16, double-buffered smem.
// Thread tile 4x8: m = ty + 32i, n = tx + 16j.
// ---------------------------------------------------------------------------
#define BKC 16
#define NCHUNK (DIN / BKC)   // 256
#define WS_STRIDE 20

__global__ void __launch_bounds__(512) gemm_eigen_kernel(
        const float* __restrict__ x,
        const float* __restrict__ w,
        const float* __restrict__ bias,
        float* __restrict__ out) {
    __shared__ float xs[2][128 * BKC];        // [m][k], row stride 16
    __shared__ float ws[2][128 * WS_STRIDE];  // [n][k], row stride 20

    int tid = threadIdx.x;
    int tx = tid & 15;        // n direction
    int ty = tid >> 4;        // m direction (0..31)
    int rowBase = blockIdx.y * 128;
    int colBase = blockIdx.x * 128;

    float accT[4][8];   // total (panel-folded) accumulator
    float accC[4][8];   // current-panel chain accumulator
#pragma unroll
    for (int i = 0; i < 4; i++)
#pragma unroll
        for (int j = 0; j < 8; j++) { accT[i][j] = 0.0f; accC[i][j] = 0.0f; }

    // staging: each thread loads 1 float4 of x and 1 of w per chunk
    int r0 = tid >> 2;        // row 0..127
    int q0 = tid & 3;         // k-quarter
    float4 xr, wr;

    // prologue: chunk 0
    xr = *(const float4*)(x + (size_t)(rowBase + r0) * DIN + q0 * 4);
    wr = *(const float4*)(w + (size_t)(colBase + r0) * DIN + q0 * 4);
    *(float4*)&xs[0][r0 * BKC + q0 * 4] = xr;
    *(float4*)&ws[0][r0 * WS_STRIDE + q0 * 4] = wr;
    __syncthreads();

    for (int c = 0; c < NCHUNK; c++) {
        int buf = c & 1;
        if (c + 1 < NCHUNK) {
            int k0 = (c + 1) * BKC;
            xr = *(const float4*)(x + (size_t)(rowBase + r0) * DIN + k0 + q0 * 4);
            wr = *(const float4*)(w + (size_t)(colBase + r0) * DIN + k0 + q0 * 4);
        }
        // ascending-k chain within the current panel
#pragma unroll
        for (int kq = 0; kq < 4; kq++) {
            float a[4][4];
#pragma unroll
            for (int i = 0; i < 4; i++)
                *(float4*)a[i] = *(const float4*)&xs[buf][(ty + 32 * i) * BKC + kq * 4];
#pragma unroll
            for (int j = 0; j < 8; j++) {
                float4 b4 = *(const float4*)&ws[buf][(tx + 16 * j) * WS_STRIDE + kq * 4];
                float bb[4] = {b4.x, b4.y, b4.z, b4.w};
#pragma unroll
                for (int kk = 0; kk < 4; kk++)
#pragma unroll
                    for (int i = 0; i < 4; i++)
                        accC[i][j] = __fmaf_rn(a[i][kk], bb[kk], accC[i][j]);
            }
        }
        // panel join: after k = 320*t (c = 19, 39, ..., 239)
        if (c % KC_BLOCKS == (KC_BLOCKS - 1) && c < 240) {
#pragma unroll
            for (int i = 0; i < 4; i++)
#pragma unroll
                for (int j = 0; j < 8; j++) {
                    accT[i][j] = accT[i][j] + accC[i][j];  // f32 add (C += panel)
                    accC[i][j] = 0.0f;
                }
        }
        __syncthreads();
        if (c + 1 < NCHUNK) {
            int nb = (c + 1) & 1;
            *(float4*)&xs[nb][r0 * BKC + q0 * 4] = xr;
            *(float4*)&ws[nb][r0 * WS_STRIDE + q0 * 4] = wr;
            __syncthreads();
        }
    }
    // tail panel (k = 3840..4095)
#pragma unroll
    for (int i = 0; i < 4; i++)
#pragma unroll
        for (int j = 0; j < 8; j++) accT[i][j] = accT[i][j] + accC[i][j];

    // epilogue: f16(matmul), then correctly-rounded f16 bias add; count pos
    int pos = 0;
#pragma unroll
    for (int i = 0; i < 4; i++) {
        int row = rowBase + ty + 32 * i;
#pragma unroll
        for (int j = 0; j < 8; j++) {
            int col = colBase + tx + 16 * j;
            __half hmm = __float2half(accT[i][j]);      // matmul rounded to f16
            float tvf = __half2float(hmm) + bias[col];  // bias is exact f16 image
            __half h = __float2half(tvf);               // f16 add (double-round safe)
            float hv = __half2float(h);
            out[OFF_TV + (size_t)row * DOUT + col] = hv;
            pos += (hv > 0.0f) ? 1 : 0;
        }
    }
#pragma unroll
    for (int off = 16; off; off >>= 1) pos += __shfl_down_sync(~0u, pos, off);
    __shared__ int spos[16];
    int warp = tid >> 5;
    if ((tid & 31) == 0) spos[warp] = pos;
    __syncthreads();
    if (tid == 0) {
        int t = 0;
        for (int i = 0; i < 16; i++) t += spos[i];
        atomicAdd(&g_pos, t);
    }
}

// ---------------------------------------------------------------------------
// limit = floor(0.2f * pos / 2048)  (match jax f32 arithmetic order)
// ---------------------------------------------------------------------------
__global__ void limit_kernel() {
    g_limit = (int)floorf((0.2f * (float)g_pos) / 2048.0f);
}

// ---------------------------------------------------------------------------
// Per-row top-`limit` mask with exact argsort tie semantics; counts[] += mask.
// One block per row; tv read from the f32 output buffer (exact f16 images).
// Order-preserving 16-bit key (bigger key = bigger value), -0 -> +0.
// ---------------------------------------------------------------------------
__device__ __forceinline__ unsigned key16f(float f) {
    unsigned short b = __half_as_ushort(__float2half(f));  // exact: f is an f16 image
    if (b == 0x8000u) b = 0;  // -0 == +0 for comparison sorts
    return (b & 0x8000u) ? (unsigned)(0xFFFFu ^ b) : (unsigned)(b | 0x8000u);
}

__global__ void topmask_kernel(const float* __restrict__ tv) {
    int row = blockIdx.x;
    int limit = g_limit;
    if (limit <= 0) return;

    __shared__ int hist[256];
    __shared__ int scan[256];
    __shared__ int sB, sChi, sK, sNeed;
    int tid = threadIdx.x;
    const float* tvr = tv + (size_t)row * DOUT;

    // Pass A: high-byte histogram
    hist[tid] = 0;
    __syncthreads();
    for (int j = tid; j < DOUT; j += 256)
        atomicAdd(&hist[key16f(tvr[j]) >> 8], 1);
    __syncthreads();
    if (tid == 0) {
        int c = 0, b = 255;
        for (; b > 0; b--) {
            if (c + hist[b] >= limit) break;
            c += hist[b];
        }
        sB = b; sChi = c;
    }
    __syncthreads();
    int b = sB, chi = sChi;

    // Pass B: low-byte histogram within bucket b
    hist[tid] = 0;
    __syncthreads();
    for (int j = tid; j < DOUT; j += 256) {
        unsigned u = key16f(tvr[j]);
        if ((int)(u >> 8) == b) atomicAdd(&hist[u & 255], 1);
    }
    __syncthreads();
    if (tid == 0) {
        int c = chi, lb = 255;
        for (; lb > 0; lb--) {
            if (c + hist[lb] >= limit) break;
            c += hist[lb];
        }
        sK = (b << 8) | lb;
        sNeed = limit - c;
    }
    __syncthreads();
    unsigned K = (unsigned)sK;
    int need = sNeed;

    // Pass C: contiguous chunks (DOUT = 256*43) so tie order == index order
    int j0 = tid * 43;
    int myTies = 0;
    for (int j = j0; j < j0 + 43; j++) {
        unsigned u = key16f(tvr[j]);
        if (u > K) atomicAdd(&g_counts[j], 1);
        else if (u == K) myTies++;
    }
    scan[tid] = myTies;
    __syncthreads();
    for (int off = 1; off < 256; off <<= 1) {
        int t = (tid >= off) ? scan[tid - off] : 0;
        __syncthreads();
        scan[tid] += t;
        __syncthreads();
    }
    int rank = scan[tid] - myTies;  // exclusive prefix: # ties with smaller index
    if (myTies > 0) {
        for (int j = j0; j < j0 + 43; j++) {
            if (key16f(tvr[j]) == K) {
                if (rank < need) atomicAdd(&g_counts[j], 1);
                rank++;
            }
        }
    }
}

// ---------------------------------------------------------------------------
// Stable top-k of counts: sort (count desc, index asc) via bitonic over 16384
// composite keys. key = (count<<14) | (16383 - j); padding keys sort last.
// Also emits filtered_bias (f32 copy) and indices (f32).
// ---------------------------------------------------------------------------
__global__ void sort_kernel(const float* __restrict__ bias, float* __restrict__ out) {
    extern __shared__ unsigned keys[];
    int tid = threadIdx.x;  // 1024 threads
    for (int i = tid; i < 16384; i += 1024) {
        int cnt = (i < DOUT) ? g_counts[i] : 0;
        keys[i] = ((unsigned)cnt << 14) | (unsigned)(16383 - i);
    }
    __syncthreads();
    for (unsigned k = 2; k <= 16384; k <<= 1) {
        for (unsigned j = k >> 1; j > 0; j >>= 1) {
            for (int i = tid; i < 16384; i += 1024) {
                unsigned ixj = (unsigned)i ^ j;
                if (ixj > (unsigned)i) {
                    unsigned a = keys[i], c = keys[ixj];
                    bool desc = ((i & k) == 0);
                    if (desc ? (a < c) : (a > c)) { keys[i] = c; keys[ixj] = a; }
                }
            }
            __syncthreads();
        }
    }
    for (int i = tid; i < REMAINED; i += 1024) {
        int idx = 16383 - (int)(keys[i] & 16383u);
        g_indices[i] = idx;
        out[OFF_BIAS + i] = bias[idx];     // exact f32 copy
        out[OFF_IDX + i]  = (float)idx;    // exact int -> f32
    }
}

// ---------------------------------------------------------------------------
// Gather filtered_W rows (raw f32 copy, 16B vectors)
// ---------------------------------------------------------------------------
__global__ void gather_kernel(const float* __restrict__ w, float* __restrict__ out) {
    int i = blockIdx.x * blockDim.x + threadIdx.x;  // 8 floats (2 float4) each
    const int total8 = REMAINED * (DIN / 8);
    if (i >= total8) return;
    int r = i / (DIN / 8);
    int c8 = i % (DIN / 8);
    int src = g_indices[r];
    const float* s = w + (size_t)src * DIN + (size_t)c8 * 8;
    float* o = out + OFF_W + (size_t)r * DIN + (size_t)c8 * 8;
    float4 v0 = *(const float4*)(s);
    float4 v1 = *(const float4*)(s + 4);
    *(float4*)(o)     = v0;
    *(float4*)(o + 4) = v1;
}

// ---------------------------------------------------------------------------
extern "C" void kernel_launch(void* const* d_in, const int* in_sizes, int n_in,
                              void* d_out, int out_size) {
    const float* x    = (const float*)d_in[0];
    const float* w    = (const float*)d_in[1];
    const float* bias = (const float*)d_in[2];
    float* out = (float*)d_out;

    cudaFuncSetAttribute(sort_kernel, cudaFuncAttributeMaxDynamicSharedMemorySize, 65536);

    init_kernel<<<(DOUT + 255) / 256, 256>>>();
    gemm_eigen_kernel<<<dim3(DOUT / 128, S_DIM / 128), 512>>>(x, w, bias, out);
    limit_kernel<<<1, 1>>>();
    topmask_kernel<<<S_DIM, 256>>>(out + OFF_TV);
    sort_kernel<<<1, 1024, 65536>>>(bias, out);
    gather_kernel<<<(REMAINED * (DIN / 8) + 255) / 256, 256>>>(w, out);
}